// round 3
// baseline (speedup 1.0000x reference)
#include <cuda_runtime.h>
#include <math.h>

#define NRES 768
#define MSAD 384
#define NH 12
#define PAIRD 128
#define OUTD 384
#define PROJ 1152
#define FINALD 2112

// ---------------- scratch (device globals; no allocation allowed) ----------
__device__ float g_wcat[MSAD * PROJ];
__device__ float g_bcat[PROJ];
__device__ float g_pw[NH];
__device__ float g_proj[NRES * PROJ];
__device__ float g_qpack[NH * NRES * 28];  // [h][i][0..15]=q*sw, [16..27]=pw*qp
__device__ float g_kpack[NH * NRES * 32];  // [h][j][0..15]=k, [16..27]=kp, [28]=-0.5*pw*|kp|^2
__device__ float g_vpack[NRES * 480];      // [j][0..191]=v [h*16+d], [192..479]=vp [h*24+p*3+c]
__device__ float g_logits[NH * NRES * NRES]; // logits, then attn in place
__device__ float g_final[NRES * FINALD];

// ---------------- K0: concat projection weights, softplus(tpw) -------------
__global__ void k0_prep(const float* __restrict__ qw, const float* __restrict__ qb,
                        const float* __restrict__ kvw, const float* __restrict__ kvb,
                        const float* __restrict__ qpw, const float* __restrict__ qpb,
                        const float* __restrict__ kvpw, const float* __restrict__ kvpb,
                        const float* __restrict__ tpw) {
    int idx = blockIdx.x * blockDim.x + threadIdx.x;
    if (idx < MSAD * PROJ) {
        int k = idx / PROJ, o = idx % PROJ;
        float v;
        if (o < 192)      v = qw[k * 192 + o];
        else if (o < 576) v = kvw[k * 384 + (o - 192)];
        else if (o < 720) v = qpw[k * 144 + (o - 576)];
        else              v = kvpw[k * 432 + (o - 720)];
        g_wcat[idx] = v;
    }
    if (idx < PROJ) {
        float b;
        if (idx < 192)      b = qb[idx];
        else if (idx < 576) b = kvb[idx - 192];
        else if (idx < 720) b = qpb[idx - 576];
        else                b = kvpb[idx - 720];
        g_bcat[idx] = b;
    }
    if (idx < NH) {
        float x = tpw[idx];
        float sp = (x > 20.f) ? x : log1pf(__expf(x));
        g_pw[idx] = sp * 0.13608276348795434f; // sqrt(1/54)
    }
}

// ---------------- K1a: projection GEMM 768x1152x384 -------------------------
__global__ __launch_bounds__(256) void k1a_gemm(const float* __restrict__ in1d) {
    __shared__ float sA[32][65];
    __shared__ float sB[32][64];
    int tid = threadIdx.x;
    int tx = tid & 15, ty = tid >> 4;
    int m0 = blockIdx.y * 64, n0 = blockIdx.x * 64;
    float acc[4][4] = {};
    for (int k0 = 0; k0 < MSAD; k0 += 32) {
        for (int idx = tid; idx < 64 * 32; idx += 256) {
            int m = idx >> 5, kk = idx & 31;
            sA[kk][m] = in1d[(m0 + m) * MSAD + k0 + kk];
        }
        for (int idx = tid; idx < 32 * 64; idx += 256) {
            int kk = idx >> 6, o = idx & 63;
            sB[kk][o] = g_wcat[(k0 + kk) * PROJ + n0 + o];
        }
        __syncthreads();
#pragma unroll
        for (int kk = 0; kk < 32; kk++) {
            float ar[4], br[4];
#pragma unroll
            for (int r = 0; r < 4; r++) ar[r] = sA[kk][ty * 4 + r];
#pragma unroll
            for (int c = 0; c < 4; c++) br[c] = sB[kk][tx * 4 + c];
#pragma unroll
            for (int r = 0; r < 4; r++)
#pragma unroll
                for (int c = 0; c < 4; c++) acc[r][c] += ar[r] * br[c];
        }
        __syncthreads();
    }
    for (int r = 0; r < 4; r++)
        for (int c = 0; c < 4; c++) {
            int m = m0 + ty * 4 + r, o = n0 + tx * 4 + c;
            g_proj[m * PROJ + o] = acc[r][c] + g_bcat[o];
        }
}

// ---------------- K1b: apply rotations, pack q/k/v --------------------------
__global__ __launch_bounds__(256) void k1b_pack(const float* __restrict__ rot,
                                                const float* __restrict__ trans) {
    __shared__ float sp[PROJ];
    __shared__ float srot[9], strans[3], spw[12];
    __shared__ float sg[192 * 3];
    int n = blockIdx.x, tid = threadIdx.x;
    for (int t = tid; t < PROJ; t += 256) sp[t] = g_proj[n * PROJ + t];
    if (tid < 9) srot[tid] = rot[n * 9 + tid];
    if (tid < 3) strans[tid] = trans[n * 3 + tid];
    if (tid < 12) spw[tid] = g_pw[tid];
    __syncthreads();

    // scalar q/k/v
    if (tid < 192) {
        int h = tid >> 4, d = tid & 15;
        g_qpack[(h * NRES + n) * 28 + d] = sp[tid] * 0.14433756729740643f; // 1/sqrt(48)
    }
    for (int t = tid; t < 384; t += 256) {
        int h = t >> 5, d = t & 31;
        if (d < 16) g_kpack[(h * NRES + n) * 32 + d] = sp[192 + t];
        else        g_vpack[n * 480 + h * 16 + (d - 16)] = sp[192 + t];
    }
    // points pass1: to_global
    if (tid < 192) {
        float l0, l1, l2;
        if (tid < 48) { l0 = sp[576 + tid]; l1 = sp[576 + 48 + tid]; l2 = sp[576 + 96 + tid]; }
        else { int vs = tid - 48; l0 = sp[720 + vs]; l1 = sp[720 + 144 + vs]; l2 = sp[720 + 288 + vs]; }
#pragma unroll
        for (int c = 0; c < 3; c++)
            sg[tid * 3 + c] = srot[c * 3 + 0] * l0 + srot[c * 3 + 1] * l1 + srot[c * 3 + 2] * l2 + strans[c];
    }
    __syncthreads();
    // pass2: pack
    if (tid < 48) {
        int h = tid >> 2, p = tid & 3;
        float pw = spw[h];
#pragma unroll
        for (int c = 0; c < 3; c++)
            g_qpack[(h * NRES + n) * 28 + 16 + p * 3 + c] = pw * sg[tid * 3 + c];
    } else if (tid < 192) {
        int vs = tid - 48, h = vs / 12, s = vs % 12;
        if (s < 4) {
#pragma unroll
            for (int c = 0; c < 3; c++)
                g_kpack[(h * NRES + n) * 32 + 16 + s * 3 + c] = sg[tid * 3 + c];
        } else {
#pragma unroll
            for (int c = 0; c < 3; c++)
                g_vpack[n * 480 + 192 + h * 24 + (s - 4) * 3 + c] = sg[tid * 3 + c];
        }
    }
    if (tid >= 192 && tid < 204) {
        int h = tid - 192;
        float s2 = 0.f;
        for (int s = 0; s < 4; s++)
            for (int c = 0; c < 3; c++) {
                float v = sg[(48 + h * 12 + s) * 3 + c];
                s2 += v * v;
            }
        g_kpack[(h * NRES + n) * 32 + 28] = -0.5f * spw[h] * s2;
    }
}

// ---------------- K2: a2d = (in2d @ W2d + b) * scale -> logits --------------
__global__ __launch_bounds__(256) void k2_a2d(const float* __restrict__ in2d,
                                              const float* __restrict__ w2d,
                                              const float* __restrict__ b2d) {
    __shared__ float sw[PAIRD * NH];
    __shared__ float sb[NH];
    int tid = threadIdx.x;
    for (int t = tid; t < PAIRD * NH; t += 256) sw[t] = w2d[t];
    if (tid < NH) sb[tid] = b2d[tid];
    __syncthreads();
    int p = blockIdx.x * 256 + tid;
    int i = p / NRES, j = p % NRES;
    const float4* row = (const float4*)(in2d + (size_t)p * PAIRD);
    const float4* sw4 = (const float4*)sw;
    float acc[12] = {};
#pragma unroll 4
    for (int c0 = 0; c0 < 32; c0++) {
        float4 a = __ldg(row + c0);
#pragma unroll
        for (int q = 0; q < 4; q++) {
            float av = (q == 0) ? a.x : (q == 1) ? a.y : (q == 2) ? a.z : a.w;
            int c = c0 * 4 + q;
            float4 w0 = sw4[c * 3 + 0], w1 = sw4[c * 3 + 1], w2 = sw4[c * 3 + 2];
            acc[0] += av * w0.x; acc[1] += av * w0.y; acc[2] += av * w0.z; acc[3] += av * w0.w;
            acc[4] += av * w1.x; acc[5] += av * w1.y; acc[6] += av * w1.z; acc[7] += av * w1.w;
            acc[8] += av * w2.x; acc[9] += av * w2.y; acc[10] += av * w2.z; acc[11] += av * w2.w;
        }
    }
#pragma unroll
    for (int h = 0; h < 12; h++)
        g_logits[(size_t)(h * NRES + i) * NRES + j] = (acc[h] + sb[h]) * 0.5773502691896258f;
}

// ---------------- K3: qk scalar+point logits + softmax ----------------------
__global__ __launch_bounds__(256) void k3_softmax() {
    __shared__ float srow[8][NRES];
    __shared__ float su[8][28];
    __shared__ float sredA[8], sredB[8];
    int h = blockIdx.y, i0 = blockIdx.x * 8;
    int tid = threadIdx.x;
    for (int t = tid; t < 8 * 28; t += 256) {
        int i8 = t / 28, d = t % 28;
        su[i8][d] = g_qpack[(size_t)(h * NRES + (i0 + i8)) * 28 + d];
    }
    __syncthreads();
    for (int jj = 0; jj < 3; jj++) {
        int j = jj * 256 + tid;
        float wr[32];
        const float4* kp4 = (const float4*)(g_kpack + (size_t)(h * NRES + j) * 32);
#pragma unroll
        for (int q = 0; q < 8; q++) {
            float4 v = kp4[q];
            wr[q * 4 + 0] = v.x; wr[q * 4 + 1] = v.y; wr[q * 4 + 2] = v.z; wr[q * 4 + 3] = v.w;
        }
#pragma unroll
        for (int i8 = 0; i8 < 8; i8++) {
            float acc = wr[28];
#pragma unroll
            for (int d = 0; d < 28; d++) acc += su[i8][d] * wr[d];
            srow[i8][j] = acc + g_logits[(size_t)(h * NRES + (i0 + i8)) * NRES + j];
        }
    }
    __syncthreads();
    int lane = tid & 31, wid = tid >> 5;
    for (int i8 = 0; i8 < 8; i8++) {
        float m = -1e30f;
#pragma unroll
        for (int jj = 0; jj < 3; jj++) m = fmaxf(m, srow[i8][jj * 256 + tid]);
#pragma unroll
        for (int o = 16; o > 0; o >>= 1) m = fmaxf(m, __shfl_xor_sync(~0u, m, o));
        if (lane == 0) sredA[wid] = m;
        __syncthreads();
        m = sredA[0];
#pragma unroll
        for (int w = 1; w < 8; w++) m = fmaxf(m, sredA[w]);
        float s = 0.f;
#pragma unroll
        for (int jj = 0; jj < 3; jj++) {
            float e = __expf(srow[i8][jj * 256 + tid] - m);
            srow[i8][jj * 256 + tid] = e;
            s += e;
        }
#pragma unroll
        for (int o = 16; o > 0; o >>= 1) s += __shfl_xor_sync(~0u, s, o);
        if (lane == 0) sredB[wid] = s;
        __syncthreads();
        s = sredB[0];
#pragma unroll
        for (int w = 1; w < 8; w++) s += sredB[w];
        float inv = 1.f / s;
#pragma unroll
        for (int jj = 0; jj < 3; jj++) {
            int j = jj * 256 + tid;
            g_logits[(size_t)(h * NRES + (i0 + i8)) * NRES + j] = srow[i8][j] * inv;
        }
        __syncthreads();
    }
}

// ---------------- K4: attention-weighted sums + epilogue pack ---------------
__global__ __launch_bounds__(256) void k4_attend(const float* __restrict__ in2d,
                                                 const float* __restrict__ rot,
                                                 const float* __restrict__ trans) {
    __shared__ float sattn[4][12][32];
    __shared__ float srpg[4 * 288];
    int i0 = blockIdx.x * 4, tid = threadIdx.x;
    int g = tid >> 6;     // h group: h = g*3 + k
    int cp = tid & 63;    // c pair: c = 2*cp
    float aov[4][3][2] = {};
    float acc_s[4] = {};
    float acc_p0[4] = {}, acc_p1[4] = {};
    int hs = tid >> 4;                     // scalar head (tid<192)
    int h_r0 = tid / 24;                   // rpg head for r=tid
    int h_r1 = (256 + tid) / 24;           // rpg head for r=256+tid (tid<32)

    for (int j0 = 0; j0 < NRES; j0 += 32) {
        for (int idx = tid; idx < 4 * 12 * 32; idx += 256) {
            int ii = idx / 384, rem = idx % 384, h = rem >> 5, jl = rem & 31;
            sattn[ii][h][jl] = g_logits[(size_t)(h * NRES + (i0 + ii)) * NRES + j0 + jl];
        }
        __syncthreads();
        for (int jl = 0; jl < 32; jl++) {
            int j = j0 + jl;
#pragma unroll
            for (int ii = 0; ii < 4; ii++) {
                float2 dv = __ldg((const float2*)(in2d + ((size_t)(i0 + ii) * NRES + j) * PAIRD + 2 * cp));
#pragma unroll
                for (int k = 0; k < 3; k++) {
                    float a = sattn[ii][g * 3 + k][jl];
                    aov[ii][k][0] += a * dv.x;
                    aov[ii][k][1] += a * dv.y;
                }
            }
            if (tid < 192) {
                float v = __ldg(g_vpack + (size_t)j * 480 + tid);
#pragma unroll
                for (int ii = 0; ii < 4; ii++) acc_s[ii] += sattn[ii][hs][jl] * v;
            }
            {
                float v0 = __ldg(g_vpack + (size_t)j * 480 + 192 + tid);
#pragma unroll
                for (int ii = 0; ii < 4; ii++) acc_p0[ii] += sattn[ii][h_r0][jl] * v0;
                if (tid < 32) {
                    float v1 = __ldg(g_vpack + (size_t)j * 480 + 192 + 256 + tid);
#pragma unroll
                    for (int ii = 0; ii < 4; ii++) acc_p1[ii] += sattn[ii][h_r1][jl] * v1;
                }
            }
        }
        __syncthreads();
    }
    // epilogue: a_over_2d
#pragma unroll
    for (int ii = 0; ii < 4; ii++)
#pragma unroll
        for (int k = 0; k < 3; k++) {
            int h = g * 3 + k, c = 2 * cp;
            float* dst = g_final + (size_t)(i0 + ii) * FINALD + 576 + h * PAIRD + c;
            dst[0] = aov[ii][k][0];
            dst[1] = aov[ii][k][1];
        }
    // result_scalar
    if (tid < 192)
        for (int ii = 0; ii < 4; ii++)
            g_final[(size_t)(i0 + ii) * FINALD + tid] = acc_s[ii];
    // rpg -> smem, rotate back to local, pnorm
    for (int ii = 0; ii < 4; ii++) srpg[ii * 288 + tid] = acc_p0[ii];
    if (tid < 32)
        for (int ii = 0; ii < 4; ii++) srpg[ii * 288 + 256 + tid] = acc_p1[ii];
    __syncthreads();
    for (int idx = tid; idx < 4 * 96; idx += 256) {
        int ii = idx / 96, d = idx % 96, n = i0 + ii;
        float vx = srpg[ii * 288 + d * 3 + 0] - trans[n * 3 + 0];
        float vy = srpg[ii * 288 + d * 3 + 1] - trans[n * 3 + 1];
        float vz = srpg[ii * 288 + d * 3 + 2] - trans[n * 3 + 2];
        float nn = 1e-8f;
#pragma unroll
        for (int ic = 0; ic < 3; ic++) {
            float rl = rot[n * 9 + 0 + ic] * vx + rot[n * 9 + 3 + ic] * vy + rot[n * 9 + 6 + ic] * vz;
            g_final[(size_t)n * FINALD + 192 + ic * 96 + d] = rl;
            nn += rl * rl;
        }
        g_final[(size_t)n * FINALD + 480 + d] = sqrtf(nn);
    }
}

// ---------------- K5: output GEMM 768x384, K=2112 ---------------------------
__global__ __launch_bounds__(256) void k5_out(const float* __restrict__ out_w,
                                              const float* __restrict__ out_b,
                                              float* __restrict__ out) {
    __shared__ float sA[32][65];
    __shared__ float sB[32][64];
    int tid = threadIdx.x, tx = tid & 15, ty = tid >> 4;
    int m0 = blockIdx.y * 64, n0 = blockIdx.x * 64;
    float acc[4][4] = {};
    for (int k0 = 0; k0 < FINALD; k0 += 32) {
        for (int idx = tid; idx < 64 * 32; idx += 256) {
            int m = idx >> 5, kk = idx & 31;
            sA[kk][m] = g_final[(size_t)(m0 + m) * FINALD + k0 + kk];
        }
        for (int idx = tid; idx < 32 * 64; idx += 256) {
            int kk = idx >> 6, o = idx & 63;
            sB[kk][o] = out_w[(size_t)(k0 + kk) * OUTD + n0 + o];
        }
        __syncthreads();
#pragma unroll
        for (int kk = 0; kk < 32; kk++) {
            float ar[4], br[4];
#pragma unroll
            for (int r = 0; r < 4; r++) ar[r] = sA[kk][ty * 4 + r];
#pragma unroll
            for (int c = 0; c < 4; c++) br[c] = sB[kk][tx * 4 + c];
#pragma unroll
            for (int r = 0; r < 4; r++)
#pragma unroll
                for (int c = 0; c < 4; c++) acc[r][c] += ar[r] * br[c];
        }
        __syncthreads();
    }
    for (int r = 0; r < 4; r++)
        for (int c = 0; c < 4; c++) {
            int m = m0 + ty * 4 + r, o = n0 + tx * 4 + c;
            out[m * OUTD + o] = acc[r][c] + out_b[o];
        }
}

// ---------------- launch ----------------------------------------------------
extern "C" void kernel_launch(void* const* d_in, const int* in_sizes, int n_in,
                              void* d_out, int out_size) {
    const float* in1d  = (const float*)d_in[0];
    const float* in2d  = (const float*)d_in[1];
    const float* rot   = (const float*)d_in[2];
    const float* trans = (const float*)d_in[3];
    const float* qw    = (const float*)d_in[4];
    const float* qb    = (const float*)d_in[5];
    const float* kvw   = (const float*)d_in[6];
    const float* kvb   = (const float*)d_in[7];
    const float* qpw   = (const float*)d_in[8];
    const float* qpb   = (const float*)d_in[9];
    const float* kvpw  = (const float*)d_in[10];
    const float* kvpb  = (const float*)d_in[11];
    const float* tpw   = (const float*)d_in[12];
    const float* w2d   = (const float*)d_in[13];
    const float* b2d   = (const float*)d_in[14];
    const float* ow    = (const float*)d_in[15];
    const float* ob    = (const float*)d_in[16];
    float* out = (float*)d_out;

    k0_prep<<<1728, 256>>>(qw, qb, kvw, kvb, qpw, qpb, kvpw, kvpb, tpw);
    k1a_gemm<<<dim3(18, 12), 256>>>(in1d);
    k1b_pack<<<768, 256>>>(rot, trans);
    k2_a2d<<<2304, 256>>>(in2d, w2d, b2d);
    k3_softmax<<<dim3(96, 12), 256>>>();
    k4_attend<<<192, 256>>>(in2d, rot, trans);
    k5_out<<<dim3(6, 12), 256>>>(ow, ob, out);
}

// round 4
// speedup vs baseline: 3.7053x; 3.7053x over previous
#include <cuda_runtime.h>
#include <math.h>

#define NRES 768
#define MSAD 384
#define NH 12
#define PAIRD 128
#define OUTD 384
#define PROJ 1152
#define FINALD 2112

typedef unsigned long long ull;

// ---------------- f32x2 helpers (Blackwell packed fp32) ---------------------
__device__ __forceinline__ ull pk2(float v) {
    ull r; asm("mov.b64 %0, {%1, %1};" : "=l"(r) : "f"(v)); return r;
}
__device__ __forceinline__ ull pk2two(float lo, float hi) {
    ull r; asm("mov.b64 %0, {%1, %2};" : "=l"(r) : "f"(lo), "f"(hi)); return r;
}
__device__ __forceinline__ void fma2(ull& d, ull a, ull b) {
    asm("fma.rn.f32x2 %0, %1, %2, %0;" : "+l"(d) : "l"(a), "l"(b));
}
__device__ __forceinline__ float2 upk(ull v) {
    float2 r; asm("mov.b64 {%0, %1}, %2;" : "=f"(r.x), "=f"(r.y) : "l"(v)); return r;
}

// ---------------- scratch (device globals; no allocation allowed) ----------
__device__ float g_wcat[MSAD * PROJ];
__device__ float g_bcat[PROJ];
__device__ float g_pw[NH];
__device__ float g_proj[NRES * PROJ];
__device__ float g_qpack[NH * NRES * 28];  // [h][i][0..15]=q*sw, [16..27]=pw*qp
__device__ float g_kpack[NH * NRES * 32];  // [h][j][0..15]=k, [16..27]=kp, [28]=-0.5*pw*|kp|^2
__device__ float g_vpack2[NH * NRES * 40]; // [h][j][0..15]=v, [16..39]=vp (p*3+c)
__device__ float g_logits[NH * NRES * NRES]; // logits, then attn in place
__device__ float g_final[NRES * FINALD];

// ---------------- K0: concat projection weights, softplus(tpw) -------------
__global__ void k0_prep(const float* __restrict__ qw, const float* __restrict__ qb,
                        const float* __restrict__ kvw, const float* __restrict__ kvb,
                        const float* __restrict__ qpw, const float* __restrict__ qpb,
                        const float* __restrict__ kvpw, const float* __restrict__ kvpb,
                        const float* __restrict__ tpw) {
    int idx = blockIdx.x * blockDim.x + threadIdx.x;
    if (idx < MSAD * PROJ) {
        int k = idx / PROJ, o = idx % PROJ;
        float v;
        if (o < 192)      v = qw[k * 192 + o];
        else if (o < 576) v = kvw[k * 384 + (o - 192)];
        else if (o < 720) v = qpw[k * 144 + (o - 576)];
        else              v = kvpw[k * 432 + (o - 720)];
        g_wcat[idx] = v;
    }
    if (idx < PROJ) {
        float b;
        if (idx < 192)      b = qb[idx];
        else if (idx < 576) b = kvb[idx - 192];
        else if (idx < 720) b = qpb[idx - 576];
        else                b = kvpb[idx - 720];
        g_bcat[idx] = b;
    }
    if (idx < NH) {
        float x = tpw[idx];
        float sp = (x > 20.f) ? x : log1pf(__expf(x));
        g_pw[idx] = sp * 0.13608276348795434f; // sqrt(1/54)
    }
}

// ---------------- K1a: projection GEMM 768x1152x384 -------------------------
__global__ __launch_bounds__(256) void k1a_gemm(const float* __restrict__ in1d) {
    __shared__ float sA[32][65];
    __shared__ float sB[32][64];
    int tid = threadIdx.x;
    int tx = tid & 15, ty = tid >> 4;
    int m0 = blockIdx.y * 64, n0 = blockIdx.x * 64;
    float acc[4][4] = {};
    for (int k0 = 0; k0 < MSAD; k0 += 32) {
        for (int idx = tid; idx < 64 * 32; idx += 256) {
            int m = idx >> 5, kk = idx & 31;
            sA[kk][m] = in1d[(m0 + m) * MSAD + k0 + kk];
        }
        for (int idx = tid; idx < 32 * 64; idx += 256) {
            int kk = idx >> 6, o = idx & 63;
            sB[kk][o] = g_wcat[(k0 + kk) * PROJ + n0 + o];
        }
        __syncthreads();
#pragma unroll
        for (int kk = 0; kk < 32; kk++) {
            float ar[4], br[4];
#pragma unroll
            for (int r = 0; r < 4; r++) ar[r] = sA[kk][ty * 4 + r];
#pragma unroll
            for (int c = 0; c < 4; c++) br[c] = sB[kk][tx * 4 + c];
#pragma unroll
            for (int r = 0; r < 4; r++)
#pragma unroll
                for (int c = 0; c < 4; c++) acc[r][c] += ar[r] * br[c];
        }
        __syncthreads();
    }
    for (int r = 0; r < 4; r++)
        for (int c = 0; c < 4; c++) {
            int m = m0 + ty * 4 + r, o = n0 + tx * 4 + c;
            g_proj[m * PROJ + o] = acc[r][c] + g_bcat[o];
        }
}

// ---------------- K1b: apply rotations, pack q/k/v --------------------------
__global__ __launch_bounds__(256) void k1b_pack(const float* __restrict__ rot,
                                                const float* __restrict__ trans) {
    __shared__ float sp[PROJ];
    __shared__ float srot[9], strans[3], spw[12];
    __shared__ float sg[192 * 3];
    int n = blockIdx.x, tid = threadIdx.x;
    for (int t = tid; t < PROJ; t += 256) sp[t] = g_proj[n * PROJ + t];
    if (tid < 9) srot[tid] = rot[n * 9 + tid];
    if (tid < 3) strans[tid] = trans[n * 3 + tid];
    if (tid < 12) spw[tid] = g_pw[tid];
    __syncthreads();

    // scalar q
    if (tid < 192) {
        int h = tid >> 4, d = tid & 15;
        g_qpack[(h * NRES + n) * 28 + d] = sp[tid] * 0.14433756729740643f; // 1/sqrt(48)
    }
    // scalar k / v
    for (int t = tid; t < 384; t += 256) {
        int h = t >> 5, d = t & 31;
        if (d < 16) g_kpack[(h * NRES + n) * 32 + d] = sp[192 + t];
        else        g_vpack2[((size_t)h * NRES + n) * 40 + (d - 16)] = sp[192 + t];
    }
    // points pass1: to_global
    if (tid < 192) {
        float l0, l1, l2;
        if (tid < 48) { l0 = sp[576 + tid]; l1 = sp[576 + 48 + tid]; l2 = sp[576 + 96 + tid]; }
        else { int vs = tid - 48; l0 = sp[720 + vs]; l1 = sp[720 + 144 + vs]; l2 = sp[720 + 288 + vs]; }
#pragma unroll
        for (int c = 0; c < 3; c++)
            sg[tid * 3 + c] = srot[c * 3 + 0] * l0 + srot[c * 3 + 1] * l1 + srot[c * 3 + 2] * l2 + strans[c];
    }
    __syncthreads();
    // pass2: pack
    if (tid < 48) {
        int h = tid >> 2, p = tid & 3;
        float pw = spw[h];
#pragma unroll
        for (int c = 0; c < 3; c++)
            g_qpack[(h * NRES + n) * 28 + 16 + p * 3 + c] = pw * sg[tid * 3 + c];
    } else if (tid < 192) {
        int vs = tid - 48, h = vs / 12, s = vs % 12;
        if (s < 4) {
#pragma unroll
            for (int c = 0; c < 3; c++)
                g_kpack[(h * NRES + n) * 32 + 16 + s * 3 + c] = sg[tid * 3 + c];
        } else {
#pragma unroll
            for (int c = 0; c < 3; c++)
                g_vpack2[((size_t)h * NRES + n) * 40 + 16 + (s - 4) * 3 + c] = sg[tid * 3 + c];
        }
    }
    if (tid >= 192 && tid < 204) {
        int h = tid - 192;
        float s2 = 0.f;
        for (int s = 0; s < 4; s++)
            for (int c = 0; c < 3; c++) {
                float v = sg[(48 + h * 12 + s) * 3 + c];
                s2 += v * v;
            }
        g_kpack[(h * NRES + n) * 32 + 28] = -0.5f * spw[h] * s2;
    }
}

// ---------------- K2: a2d = (in2d @ W2d + b) * scale -> logits --------------
// Tiled GEMM: 256 rows/block staged through smem; thread = one row; no
// cross-lane reduction. f32x2 over h-pairs.
__global__ __launch_bounds__(256) void k2_a2d(const float* __restrict__ in2d,
                                              const float* __restrict__ w2d,
                                              const float* __restrict__ b2d) {
    __shared__ float sA[256][33];
    __shared__ ull sw2[128][6];
    __shared__ float sb[12];
    int tid = threadIdx.x;
    for (int f = tid; f < 128 * 6; f += 256) {
        int c = f / 6, hp = f % 6;
        float2 w = *(const float2*)(w2d + c * 12 + hp * 2);
        sw2[c][hp] = pk2two(w.x, w.y);
    }
    if (tid < 12) sb[tid] = b2d[tid];
    size_t p0 = (size_t)blockIdx.x * 256;
    ull acc[6] = {};
    for (int k0 = 0; k0 < 128; k0 += 32) {
        __syncthreads();
        for (int f = tid; f < 2048; f += 256) {
            int r = f >> 3, c4 = f & 7;
            float4 v = __ldg((const float4*)(in2d + (p0 + r) * 128 + k0) + c4);
            sA[r][c4 * 4 + 0] = v.x; sA[r][c4 * 4 + 1] = v.y;
            sA[r][c4 * 4 + 2] = v.z; sA[r][c4 * 4 + 3] = v.w;
        }
        __syncthreads();
#pragma unroll
        for (int k = 0; k < 32; k++) {
            float a = sA[tid][k];
            ull a2 = pk2(a);
            ulonglong2 w01 = *(const ulonglong2*)&sw2[k0 + k][0];
            ulonglong2 w23 = *(const ulonglong2*)&sw2[k0 + k][2];
            ulonglong2 w45 = *(const ulonglong2*)&sw2[k0 + k][4];
            fma2(acc[0], a2, w01.x); fma2(acc[1], a2, w01.y);
            fma2(acc[2], a2, w23.x); fma2(acc[3], a2, w23.y);
            fma2(acc[4], a2, w45.x); fma2(acc[5], a2, w45.y);
        }
    }
    size_t p = p0 + tid;
    int i = (int)(p / NRES), j = (int)(p % NRES);
    float res[12];
#pragma unroll
    for (int hp = 0; hp < 6; hp++) {
        float2 v = upk(acc[hp]);
        res[2 * hp] = v.x; res[2 * hp + 1] = v.y;
    }
#pragma unroll
    for (int h = 0; h < 12; h++)
        g_logits[((size_t)h * NRES + i) * NRES + j] = (res[h] + sb[h]) * 0.5773502691896258f;
}

// ---------------- K3: qk scalar+point logits + softmax ----------------------
__global__ __launch_bounds__(256) void k3_softmax() {
    __shared__ float srow[8][NRES];
    __shared__ float su[8][28];
    __shared__ float sredA[8], sredB[8];
    int h = blockIdx.y, i0 = blockIdx.x * 8;
    int tid = threadIdx.x;
    for (int t = tid; t < 8 * 28; t += 256) {
        int i8 = t / 28, d = t % 28;
        su[i8][d] = g_qpack[(size_t)(h * NRES + (i0 + i8)) * 28 + d];
    }
    __syncthreads();
    for (int jj = 0; jj < 3; jj++) {
        int j = jj * 256 + tid;
        float wr[32];
        const float4* kp4 = (const float4*)(g_kpack + (size_t)(h * NRES + j) * 32);
#pragma unroll
        for (int q = 0; q < 8; q++) {
            float4 v = kp4[q];
            wr[q * 4 + 0] = v.x; wr[q * 4 + 1] = v.y; wr[q * 4 + 2] = v.z; wr[q * 4 + 3] = v.w;
        }
#pragma unroll
        for (int i8 = 0; i8 < 8; i8++) {
            float acc = wr[28];
#pragma unroll
            for (int d = 0; d < 28; d++) acc += su[i8][d] * wr[d];
            srow[i8][j] = acc + g_logits[(size_t)(h * NRES + (i0 + i8)) * NRES + j];
        }
    }
    __syncthreads();
    int lane = tid & 31, wid = tid >> 5;
    for (int i8 = 0; i8 < 8; i8++) {
        float m = -1e30f;
#pragma unroll
        for (int jj = 0; jj < 3; jj++) m = fmaxf(m, srow[i8][jj * 256 + tid]);
#pragma unroll
        for (int o = 16; o > 0; o >>= 1) m = fmaxf(m, __shfl_xor_sync(~0u, m, o));
        if (lane == 0) sredA[wid] = m;
        __syncthreads();
        m = sredA[0];
#pragma unroll
        for (int w = 1; w < 8; w++) m = fmaxf(m, sredA[w]);
        float s = 0.f;
#pragma unroll
        for (int jj = 0; jj < 3; jj++) {
            float e = __expf(srow[i8][jj * 256 + tid] - m);
            srow[i8][jj * 256 + tid] = e;
            s += e;
        }
#pragma unroll
        for (int o = 16; o > 0; o >>= 1) s += __shfl_xor_sync(~0u, s, o);
        if (lane == 0) sredB[wid] = s;
        __syncthreads();
        s = sredB[0];
#pragma unroll
        for (int w = 1; w < 8; w++) s += sredB[w];
        float inv = 1.f / s;
#pragma unroll
        for (int jj = 0; jj < 3; jj++) {
            int j = jj * 256 + tid;
            g_logits[(size_t)(h * NRES + (i0 + i8)) * NRES + j] = srow[i8][j] * inv;
        }
        __syncthreads();
    }
}

// ---------------- K4a: a_over_2d — one block per query row i ----------------
// 128 threads: g = tid>>6 (2 groups of 6 heads), cp = tid&63 (c pair).
__global__ __launch_bounds__(128) void k4a_aover(const float* __restrict__ in2d) {
    __shared__ float sattn[12][768];
    int i = blockIdx.x, tid = threadIdx.x;
    for (int f = tid; f < 2304; f += 128) {  // 12*768/4 float4
        int h = f / 192, q = f % 192;
        ((float4*)&sattn[h][0])[q] =
            __ldg((const float4*)(g_logits + ((size_t)h * NRES + i) * NRES) + q);
    }
    __syncthreads();
    int g = tid >> 6, cp = tid & 63;
    const float* base = in2d + (size_t)i * (NRES * PAIRD) + 2 * cp;
    ull acc[6] = {};
    for (int j = 0; j < NRES; j += 8) {
        ull d[8];
#pragma unroll
        for (int u = 0; u < 8; u++)
            d[u] = __ldg((const ull*)(base + (size_t)(j + u) * PAIRD));
#pragma unroll
        for (int k = 0; k < 6; k++) {
            const float* ap = &sattn[g * 6 + k][j];
            float4 A0 = *(const float4*)ap;
            float4 A1 = *(const float4*)(ap + 4);
            fma2(acc[k], pk2(A0.x), d[0]); fma2(acc[k], pk2(A0.y), d[1]);
            fma2(acc[k], pk2(A0.z), d[2]); fma2(acc[k], pk2(A0.w), d[3]);
            fma2(acc[k], pk2(A1.x), d[4]); fma2(acc[k], pk2(A1.y), d[5]);
            fma2(acc[k], pk2(A1.z), d[6]); fma2(acc[k], pk2(A1.w), d[7]);
        }
    }
#pragma unroll
    for (int k = 0; k < 6; k++) {
        int h = g * 6 + k;
        float2 v = upk(acc[k]);
        float* dst = g_final + (size_t)i * FINALD + 576 + h * PAIRD + 2 * cp;
        dst[0] = v.x; dst[1] = v.y;
    }
}

// ---------------- K4b: per-head GEMM for v / vp + rotate-back epilogue ------
// grid (12 itiles, 12 h); 320 threads: il = tid&63 (i row), dg = tid>>6 (d octet)
__global__ __launch_bounds__(320) void k4b_vattend(const float* __restrict__ rot,
                                                   const float* __restrict__ trans) {
    __shared__ float2 sattn2[64][65];
    __shared__ ull svp[64 * 20];       // [jj][40 floats] as 20 ull
    __shared__ float srpg[64][24];
    int i0 = blockIdx.x * 64, h = blockIdx.y;
    int tid = threadIdx.x, il = tid & 63, dg = tid >> 6;
    ull acc[4] = {};
    for (int j0 = 0; j0 < NRES; j0 += 64) {
        for (int f = tid; f < 4096; f += 320) {
            int r = f >> 6, c = f & 63;
            float a = g_logits[((size_t)h * NRES + i0 + r) * NRES + j0 + c];
            sattn2[r][c] = make_float2(a, a);
        }
        for (int f = tid; f < 1280; f += 320)
            svp[f] = __ldg((const ull*)(g_vpack2 + ((size_t)h * NRES + j0) * 40) + f);
        __syncthreads();
#pragma unroll 4
        for (int jj = 0; jj < 64; jj++) {
            ull a2 = *(const ull*)&sattn2[il][jj];
            const ulonglong2* w = (const ulonglong2*)&svp[jj * 20 + dg * 4];
            ulonglong2 w01 = w[0], w23 = w[1];
            fma2(acc[0], a2, w01.x); fma2(acc[1], a2, w01.y);
            fma2(acc[2], a2, w23.x); fma2(acc[3], a2, w23.y);
        }
        __syncthreads();
    }
    int n_i = i0 + il;
    float v[8];
#pragma unroll
    for (int q = 0; q < 4; q++) {
        float2 t = upk(acc[q]);
        v[2 * q] = t.x; v[2 * q + 1] = t.y;
    }
    if (dg < 2) {
        float* dst = g_final + (size_t)n_i * FINALD + h * 16 + dg * 8;
#pragma unroll
        for (int t = 0; t < 8; t++) dst[t] = v[t];
    } else {
        int d0 = (dg - 2) * 8;
#pragma unroll
        for (int t = 0; t < 8; t++) srpg[il][d0 + t] = v[t];
    }
    __syncthreads();
    for (int f = tid; f < 512; f += 320) {
        int ii = f >> 3, p = f & 7;
        int n = i0 + ii;
        float vx = srpg[ii][p * 3 + 0] - trans[n * 3 + 0];
        float vy = srpg[ii][p * 3 + 1] - trans[n * 3 + 1];
        float vz = srpg[ii][p * 3 + 2] - trans[n * 3 + 2];
        float nn = 1e-8f;
#pragma unroll
        for (int ic = 0; ic < 3; ic++) {
            float rl = rot[n * 9 + 0 + ic] * vx + rot[n * 9 + 3 + ic] * vy + rot[n * 9 + 6 + ic] * vz;
            g_final[(size_t)n * FINALD + 192 + ic * 96 + h * 8 + p] = rl;
            nn += rl * rl;
        }
        g_final[(size_t)n * FINALD + 480 + h * 8 + p] = sqrtf(nn);
    }
}

// ---------------- K5: output GEMM 768x384, K=2112 ---------------------------
__global__ __launch_bounds__(256) void k5_out(const float* __restrict__ out_w,
                                              const float* __restrict__ out_b,
                                              float* __restrict__ out) {
    __shared__ float sA[32][65];
    __shared__ float sB[32][64];
    int tid = threadIdx.x, tx = tid & 15, ty = tid >> 4;
    int m0 = blockIdx.y * 64, n0 = blockIdx.x * 64;
    float acc[4][4] = {};
    for (int k0 = 0; k0 < FINALD; k0 += 32) {
        for (int idx = tid; idx < 64 * 32; idx += 256) {
            int m = idx >> 5, kk = idx & 31;
            sA[kk][m] = g_final[(size_t)(m0 + m) * FINALD + k0 + kk];
        }
        for (int idx = tid; idx < 32 * 64; idx += 256) {
            int kk = idx >> 6, o = idx & 63;
            sB[kk][o] = out_w[(size_t)(k0 + kk) * OUTD + n0 + o];
        }
        __syncthreads();
#pragma unroll
        for (int kk = 0; kk < 32; kk++) {
            float ar[4], br[4];
#pragma unroll
            for (int r = 0; r < 4; r++) ar[r] = sA[kk][ty * 4 + r];
#pragma unroll
            for (int c = 0; c < 4; c++) br[c] = sB[kk][tx * 4 + c];
#pragma unroll
            for (int r = 0; r < 4; r++)
#pragma unroll
                for (int c = 0; c < 4; c++) acc[r][c] += ar[r] * br[c];
        }
        __syncthreads();
    }
    for (int r = 0; r < 4; r++)
        for (int c = 0; c < 4; c++) {
            int m = m0 + ty * 4 + r, o = n0 + tx * 4 + c;
            out[m * OUTD + o] = acc[r][c] + out_b[o];
        }
}

// ---------------- launch ----------------------------------------------------
extern "C" void kernel_launch(void* const* d_in, const int* in_sizes, int n_in,
                              void* d_out, int out_size) {
    const float* in1d  = (const float*)d_in[0];
    const float* in2d  = (const float*)d_in[1];
    const float* rot   = (const float*)d_in[2];
    const float* trans = (const float*)d_in[3];
    const float* qw    = (const float*)d_in[4];
    const float* qb    = (const float*)d_in[5];
    const float* kvw   = (const float*)d_in[6];
    const float* kvb   = (const float*)d_in[7];
    const float* qpw   = (const float*)d_in[8];
    const float* qpb   = (const float*)d_in[9];
    const float* kvpw  = (const float*)d_in[10];
    const float* kvpb  = (const float*)d_in[11];
    const float* tpw   = (const float*)d_in[12];
    const float* w2d   = (const float*)d_in[13];
    const float* b2d   = (const float*)d_in[14];
    const float* ow    = (const float*)d_in[15];
    const float* ob    = (const float*)d_in[16];
    float* out = (float*)d_out;

    k0_prep<<<1728, 256>>>(qw, qb, kvw, kvb, qpw, qpb, kvpw, kvpb, tpw);
    k1a_gemm<<<dim3(18, 12), 256>>>(in1d);
    k1b_pack<<<768, 256>>>(rot, trans);
    k2_a2d<<<2304, 256>>>(in2d, w2d, b2d);
    k3_softmax<<<dim3(96, 12), 256>>>();
    k4a_aover<<<768, 128>>>(in2d);
    k4b_vattend<<<dim3(12, 12), 320>>>(rot, trans);
    k5_out<<<dim3(6, 12), 256>>>(ow, ob, out);
}